// round 1
// baseline (speedup 1.0000x reference)
#include <cuda_runtime.h>
#include <math.h>

#define M_DIM 1024      // B
#define U_DIM 2048      // U
#define N_DIM 8192      // 4U (gate columns)
#define K_DIM 4096      // 2U (concat depth)

// Scratch for the raw GEMM result ifgo = [x|h] @ w  (32 MB, static device array)
__device__ float g_scratch[(size_t)M_DIM * N_DIM];

// ---------------------------------------------------------------------------
// Kernel 1: SGEMM  C[1024,8192] = A[1024,4096] @ W[4096,8192]
// A is the virtual concat of x and h (handled by k-tile base-pointer select;
// K-tiles of 16 never straddle the 2048 boundary).
// 128x128 CTA tile, BK=16, 8x8 per-thread register tile, 256 threads.
// ---------------------------------------------------------------------------
__global__ __launch_bounds__(256)
void sgemm_xh_w(const float* __restrict__ x,
                const float* __restrict__ h,
                const float* __restrict__ w)
{
    __shared__ float As[16][132];   // transposed A tile, padded to cut STS conflicts
    __shared__ float Bs[16][128];

    const int tid = threadIdx.x;
    const int bm  = blockIdx.y * 128;
    const int bn  = blockIdx.x * 128;

    const int ty = tid >> 4;            // 0..15 (m direction)
    const int tx = tid & 15;            // 0..15 (n direction)

    const int arow = tid >> 2;          // 0..63
    const int acol = (tid & 3) << 2;    // 0,4,8,12
    const int brow = tid >> 5;          // 0..7
    const int bcol = (tid & 31) << 2;   // 0..124

    float acc[8][8];
    #pragma unroll
    for (int i = 0; i < 8; ++i)
        #pragma unroll
        for (int j = 0; j < 8; ++j) acc[i][j] = 0.0f;

    for (int k0 = 0; k0 < K_DIM; k0 += 16) {
        // Which half of the concat does this k-tile live in?
        const float* Abase = (k0 < U_DIM) ? (x + k0) : (h + (k0 - U_DIM));

        // Load A tile 128x16 (two rows of float4 per thread), store transposed
        #pragma unroll
        for (int r = 0; r < 2; ++r) {
            int row = arow + r * 64;
            float4 v = *reinterpret_cast<const float4*>(
                Abase + (size_t)(bm + row) * U_DIM + acol);
            As[acol + 0][row] = v.x;
            As[acol + 1][row] = v.y;
            As[acol + 2][row] = v.z;
            As[acol + 3][row] = v.w;
        }
        // Load B tile 16x128 (two float4 per thread), direct layout
        #pragma unroll
        for (int r = 0; r < 2; ++r) {
            int row = brow + r * 8;
            float4 v = *reinterpret_cast<const float4*>(
                w + (size_t)(k0 + row) * N_DIM + bn + bcol);
            *reinterpret_cast<float4*>(&Bs[row][bcol]) = v;
        }
        __syncthreads();

        #pragma unroll
        for (int kk = 0; kk < 16; ++kk) {
            float a[8], b[8];
            #pragma unroll
            for (int i = 0; i < 8; ++i) a[i] = As[kk][ty * 8 + i];
            #pragma unroll
            for (int j = 0; j < 8; ++j) b[j] = Bs[kk][tx * 8 + j];
            #pragma unroll
            for (int i = 0; i < 8; ++i)
                #pragma unroll
                for (int j = 0; j < 8; ++j)
                    acc[i][j] = fmaf(a[i], b[j], acc[i][j]);
        }
        __syncthreads();
    }

    // Write the raw gate pre-activations to scratch (float4 stores)
    #pragma unroll
    for (int i = 0; i < 8; ++i) {
        size_t row = (size_t)(bm + ty * 8 + i);
        float4* dst = reinterpret_cast<float4*>(
            &g_scratch[row * N_DIM + bn + tx * 8]);
        dst[0] = make_float4(acc[i][0], acc[i][1], acc[i][2], acc[i][3]);
        dst[1] = make_float4(acc[i][4], acc[i][5], acc[i][6], acc[i][7]);
    }
}

// ---------------------------------------------------------------------------
// Kernel 2: gate activations + cell update + output writes
// out layout: [h_new | h_new | c_new], each B*U floats
// ---------------------------------------------------------------------------
__device__ __forceinline__ float sigmoidf_(float v) {
    return 1.0f / (1.0f + expf(-v));
}

__global__ __launch_bounds__(256)
void lstm_epilogue(const float* __restrict__ c, float* __restrict__ out)
{
    const int BU = M_DIM * U_DIM;
    int t = blockIdx.x * blockDim.x + threadIdx.x;   // float4 index
    if (t >= BU / 4) return;
    int idx = t << 2;
    int m = idx >> 11;          // / 2048
    int u = idx & 2047;         // % 2048
    size_t base = (size_t)m * N_DIM + u;

    float4 iv = *reinterpret_cast<const float4*>(&g_scratch[base]);
    float4 fv = *reinterpret_cast<const float4*>(&g_scratch[base + 2048]);
    float4 gv = *reinterpret_cast<const float4*>(&g_scratch[base + 4096]);
    float4 ov = *reinterpret_cast<const float4*>(&g_scratch[base + 6144]);
    float4 cv = *reinterpret_cast<const float4*>(c + idx);

    float ia[4] = {iv.x, iv.y, iv.z, iv.w};
    float fa[4] = {fv.x, fv.y, fv.z, fv.w};
    float ga[4] = {gv.x, gv.y, gv.z, gv.w};
    float oa[4] = {ov.x, ov.y, ov.z, ov.w};
    float ca[4] = {cv.x, cv.y, cv.z, cv.w};

    float hn[4], cn[4];
    #pragma unroll
    for (int j = 0; j < 4; ++j) {
        float ig = sigmoidf_(ia[j]);
        float fg = sigmoidf_(fa[j]);
        float og = sigmoidf_(oa[j]);
        float gg = tanhf(ga[j]);
        cn[j] = fg * ca[j] + ig * gg;
        hn[j] = og * tanhf(cn[j]);
    }

    float4 h4 = make_float4(hn[0], hn[1], hn[2], hn[3]);
    float4 c4 = make_float4(cn[0], cn[1], cn[2], cn[3]);

    *reinterpret_cast<float4*>(out + idx)            = h4;   // h_new (copy 1)
    *reinterpret_cast<float4*>(out + BU + idx)       = h4;   // h_new (copy 2)
    *reinterpret_cast<float4*>(out + 2 * BU + idx)   = c4;   // c_new
}

// ---------------------------------------------------------------------------
extern "C" void kernel_launch(void* const* d_in, const int* in_sizes, int n_in,
                              void* d_out, int out_size)
{
    const float* x = (const float*)d_in[0];
    const float* h = (const float*)d_in[1];
    const float* c = (const float*)d_in[2];
    const float* w = (const float*)d_in[3];
    float* out = (float*)d_out;

    dim3 grid(N_DIM / 128, M_DIM / 128);   // (64, 8)
    sgemm_xh_w<<<grid, 256>>>(x, h, w);

    int n4 = (M_DIM * U_DIM) / 4;          // 524288
    lstm_epilogue<<<(n4 + 255) / 256, 256>>>(c, out);
}

// round 3
// speedup vs baseline: 2.8361x; 2.8361x over previous
#include <cuda_runtime.h>
#include <cstdint>
#include <math.h>

#define M_DIM 1024
#define U_DIM 2048
#define N_DIM 8192
#define K_DIM 4096

#define BM 128
#define BUT 32                      // u-tile (per gate)
#define BK 32
#define STAGES 4
#define SA 36                       // A smem row stride (floats), pad for bank-free frags
#define SB 136                      // B smem row stride (floats)
#define A_WORDS (BM * SA)           // 4608
#define B_WORDS (BK * SB)           // 4352
#define STG_WORDS (A_WORDS + B_WORDS)   // 8960
#define SMEM_BYTES (STAGES * STG_WORDS * 4)  // 143360
#define EP_STRIDE 132
#define NKT (K_DIM / BK)            // 128

// ---------------------------------------------------------------------------
__device__ __forceinline__ void cp16(uint32_t dst, const float* src) {
    asm volatile("cp.async.cg.shared.global [%0], [%1], 16;" :: "r"(dst), "l"(src));
}
#define CP_COMMIT() asm volatile("cp.async.commit_group;" ::: "memory")
#define CP_WAIT2()  asm volatile("cp.async.wait_group 2;" ::: "memory")

__device__ __forceinline__ uint32_t f2tf(float v) {
    uint32_t r;
    asm("cvt.rna.tf32.f32 %0, %1;" : "=r"(r) : "f"(v));
    return r;
}

__device__ __forceinline__ void mma8(float* d, const uint32_t* a, const uint32_t* b) {
    asm volatile(
        "mma.sync.aligned.m16n8k8.row.col.f32.tf32.tf32.f32 "
        "{%0,%1,%2,%3}, {%4,%5,%6,%7}, {%8,%9}, {%0,%1,%2,%3};"
        : "+f"(d[0]), "+f"(d[1]), "+f"(d[2]), "+f"(d[3])
        : "r"(a[0]), "r"(a[1]), "r"(a[2]), "r"(a[3]), "r"(b[0]), "r"(b[1]));
}

__device__ __forceinline__ float sigmoidf_(float v) { return 1.0f / (1.0f + expf(-v)); }

// ---------------------------------------------------------------------------
// Load one pipeline stage: A tile [128 m x 32 k], B tile [32 k x (4 gates x 32 u)]
// 2048 x 16B cp.async, 8 per thread, globally coalesced.
// ---------------------------------------------------------------------------
__device__ __forceinline__ void load_stage(float* smem, int s, int kt,
                                           int bm, int bu,
                                           const float* __restrict__ x,
                                           const float* __restrict__ h,
                                           const float* __restrict__ w,
                                           int tid) {
    const int k0 = kt * BK;
    const float* A = (k0 < U_DIM) ? (x + k0) : (h + (k0 - U_DIM));
    uint32_t sA = (uint32_t)__cvta_generic_to_shared(smem + s * STG_WORDS);
    uint32_t sB = sA + A_WORDS * 4;

    #pragma unroll
    for (int i = 0; i < 4; ++i) {                 // A: 1024 chunks
        int id = tid + i * 256;
        int row = id >> 3, ch = id & 7;           // 8 x 16B per 128B row
        cp16(sA + (row * SA + ch * 4) * 4,
             A + (size_t)(bm + row) * U_DIM + ch * 4);
    }
    #pragma unroll
    for (int i = 0; i < 4; ++i) {                 // B: 1024 chunks
        int id = tid + i * 256;
        int kr = id >> 5, rem = id & 31;
        int gate = rem >> 3, ch = rem & 7;
        cp16(sB + (kr * SB + gate * 32 + ch * 4) * 4,
             w + (size_t)(k0 + kr) * N_DIM + gate * U_DIM + bu + ch * 4);
    }
}

// ---------------------------------------------------------------------------
// Fused kernel: tf32 mma.sync GEMM (per-CTA 128m x {i,f,g,o}x32u) + LSTM gating
// ---------------------------------------------------------------------------
__global__ __launch_bounds__(256, 1)
void lstm_fused(const float* __restrict__ x, const float* __restrict__ h,
                const float* __restrict__ c, const float* __restrict__ w,
                float* __restrict__ out) {
    extern __shared__ float smem[];
    const int tid = threadIdx.x;
    const int wid = tid >> 5, lane = tid & 31;
    const int g = lane >> 2, t = lane & 3;        // mma lane decomposition
    const int wm = wid >> 2, wn = wid & 3;        // 2 x 4 warp grid
    const int bm = blockIdx.x * BM;               // m tile (x fastest: wave shares W)
    const int bu = blockIdx.y * BUT;              // u tile

    float acc[4][4][4];
    #pragma unroll
    for (int mi = 0; mi < 4; ++mi)
        #pragma unroll
        for (int ni = 0; ni < 4; ++ni)
            #pragma unroll
            for (int q = 0; q < 4; ++q) acc[mi][ni][q] = 0.0f;

    // prologue: fill 3 stages
    #pragma unroll
    for (int s = 0; s < 3; ++s) {
        load_stage(smem, s, s, bm, bu, x, h, w, tid);
        CP_COMMIT();
    }

    for (int kt = 0; kt < NKT; ++kt) {
        CP_WAIT2();
        __syncthreads();
        if (kt + 3 < NKT)
            load_stage(smem, (kt + 3) & 3, kt + 3, bm, bu, x, h, w, tid);
        CP_COMMIT();

        const float* sa = smem + (kt & 3) * STG_WORDS;
        const float* sb = sa + A_WORDS;

        #pragma unroll
        for (int k8 = 0; k8 < 4; ++k8) {
            const int kb = k8 * 8;
            uint32_t af[4][4];
            #pragma unroll
            for (int mi = 0; mi < 4; ++mi) {
                const int rm = wm * 64 + mi * 16;
                af[mi][0] = f2tf(sa[(rm + g) * SA + kb + t]);
                af[mi][1] = f2tf(sa[(rm + g + 8) * SA + kb + t]);
                af[mi][2] = f2tf(sa[(rm + g) * SA + kb + t + 4]);
                af[mi][3] = f2tf(sa[(rm + g + 8) * SA + kb + t + 4]);
            }
            uint32_t bf[4][2];
            #pragma unroll
            for (int ni = 0; ni < 4; ++ni) {
                const int cb = wn * 32 + ni * 8 + g;
                bf[ni][0] = f2tf(sb[(kb + t) * SB + cb]);
                bf[ni][1] = f2tf(sb[(kb + t + 4) * SB + cb]);
            }
            #pragma unroll
            for (int mi = 0; mi < 4; ++mi)
                #pragma unroll
                for (int ni = 0; ni < 4; ++ni)
                    mma8(acc[mi][ni], af[mi], bf[ni]);
        }
    }

    // ------------- epilogue: gather gates via smem, gate, write out ---------
    __syncthreads();
    float* se = smem;                             // reuse pipeline smem
    #pragma unroll
    for (int mi = 0; mi < 4; ++mi) {
        const int r0 = wm * 64 + mi * 16 + g;
        #pragma unroll
        for (int ni = 0; ni < 4; ++ni) {
            const int cb = wn * 32 + ni * 8 + 2 * t;
            *reinterpret_cast<float2*>(&se[r0 * EP_STRIDE + cb]) =
                make_float2(acc[mi][ni][0], acc[mi][ni][1]);
            *reinterpret_cast<float2*>(&se[(r0 + 8) * EP_STRIDE + cb]) =
                make_float2(acc[mi][ni][2], acc[mi][ni][3]);
        }
    }
    __syncthreads();

    const int BUsz = M_DIM * U_DIM;
    const int c4 = tid & 7;
    #pragma unroll
    for (int rep = 0; rep < 4; ++rep) {
        const int r = (tid >> 3) + rep * 32;
        const float* row = &se[r * EP_STRIDE];
        float4 iv = *reinterpret_cast<const float4*>(row + 0 * 32 + c4 * 4);
        float4 fv = *reinterpret_cast<const float4*>(row + 1 * 32 + c4 * 4);
        float4 gv = *reinterpret_cast<const float4*>(row + 2 * 32 + c4 * 4);
        float4 ov = *reinterpret_cast<const float4*>(row + 3 * 32 + c4 * 4);
        const size_t gidx = (size_t)(bm + r) * U_DIM + bu + c4 * 4;
        float4 cv = *reinterpret_cast<const float4*>(c + gidx);

        float ia[4] = {iv.x, iv.y, iv.z, iv.w};
        float fa[4] = {fv.x, fv.y, fv.z, fv.w};
        float ga[4] = {gv.x, gv.y, gv.z, gv.w};
        float oa[4] = {ov.x, ov.y, ov.z, ov.w};
        float ca[4] = {cv.x, cv.y, cv.z, cv.w};
        float hn[4], cn[4];
        #pragma unroll
        for (int q = 0; q < 4; ++q) {
            float ig = sigmoidf_(ia[q]);
            float fg = sigmoidf_(fa[q]);
            float og = sigmoidf_(oa[q]);
            float gg = tanhf(ga[q]);
            cn[q] = fg * ca[q] + ig * gg;
            hn[q] = og * tanhf(cn[q]);
        }
        float4 h4 = make_float4(hn[0], hn[1], hn[2], hn[3]);
        float4 cc4 = make_float4(cn[0], cn[1], cn[2], cn[3]);
        *reinterpret_cast<float4*>(out + gidx)            = h4;
        *reinterpret_cast<float4*>(out + BUsz + gidx)     = h4;
        *reinterpret_cast<float4*>(out + 2 * BUsz + gidx) = cc4;
    }
}

// ---------------------------------------------------------------------------
extern "C" void kernel_launch(void* const* d_in, const int* in_sizes, int n_in,
                              void* d_out, int out_size) {
    const float* x = (const float*)d_in[0];
    const float* h = (const float*)d_in[1];
    const float* c = (const float*)d_in[2];
    const float* w = (const float*)d_in[3];
    float* out = (float*)d_out;

    static int configured = 0;
    if (!configured) {
        cudaFuncSetAttribute(lstm_fused,
                             cudaFuncAttributeMaxDynamicSharedMemorySize,
                             SMEM_BYTES);
        configured = 1;
    }

    dim3 grid(M_DIM / BM, U_DIM / BUT);   // (8, 64); x fastest -> W L2 reuse
    lstm_fused<<<grid, 256, SMEM_BYTES>>>(x, h, c, w, out);
}

// round 4
// speedup vs baseline: 3.3111x; 1.1675x over previous
#include <cuda_runtime.h>
#include <cstdint>
#include <math.h>

#define M_DIM 1024
#define U_DIM 2048
#define N_DIM 8192
#define K_DIM 4096

#define BM 128
#define BUT 32                      // u-tile (per gate)
#define BK 32
#define STAGES 3
#define SA 36                       // A smem row stride (floats)
#define SB 136                      // B smem row stride (floats)
#define A_WORDS (BM * SA)           // 4608
#define B_WORDS (BK * SB)           // 4352
#define STG_WORDS (A_WORDS + B_WORDS)        // 8960
#define SMEM_BYTES (STAGES * STG_WORDS * 4)  // 107520 -> 2 CTAs/SM
#define EP_STRIDE 132
#define NKT (K_DIM / BK)            // 128

// ---------------------------------------------------------------------------
__device__ __forceinline__ void cp16(uint32_t dst, const float* src) {
    asm volatile("cp.async.cg.shared.global [%0], [%1], 16;" :: "r"(dst), "l"(src));
}
#define CP_COMMIT() asm volatile("cp.async.commit_group;" ::: "memory")
#define CP_WAIT1()  asm volatile("cp.async.wait_group 1;" ::: "memory")

__device__ __forceinline__ uint32_t f2tf(float v) {
    uint32_t r;
    asm("cvt.rna.tf32.f32 %0, %1;" : "=r"(r) : "f"(v));
    return r;
}

__device__ __forceinline__ void mma8(float* d, const uint32_t* a, const uint32_t* b) {
    asm volatile(
        "mma.sync.aligned.m16n8k8.row.col.f32.tf32.tf32.f32 "
        "{%0,%1,%2,%3}, {%4,%5,%6,%7}, {%8,%9}, {%0,%1,%2,%3};"
        : "+f"(d[0]), "+f"(d[1]), "+f"(d[2]), "+f"(d[3])
        : "r"(a[0]), "r"(a[1]), "r"(a[2]), "r"(a[3]), "r"(b[0]), "r"(b[1]));
}

__device__ __forceinline__ float sigmoidf_(float v) { return 1.0f / (1.0f + expf(-v)); }

// ---------------------------------------------------------------------------
// Load one pipeline stage: A tile [128 m x 32 k], B tile [32 k x (4 gates x 32 u)]
// ---------------------------------------------------------------------------
__device__ __forceinline__ void load_stage(float* smem, int s, int kt,
                                           int bm, int bu,
                                           const float* __restrict__ x,
                                           const float* __restrict__ h,
                                           const float* __restrict__ w,
                                           int tid) {
    const int k0 = kt * BK;
    const float* A = (k0 < U_DIM) ? (x + k0) : (h + (k0 - U_DIM));
    uint32_t sA = (uint32_t)__cvta_generic_to_shared(smem + s * STG_WORDS);
    uint32_t sB = sA + A_WORDS * 4;

    #pragma unroll
    for (int i = 0; i < 4; ++i) {                 // A: 1024 x 16B chunks
        int id = tid + i * 256;
        int row = id >> 3, ch = id & 7;
        cp16(sA + (row * SA + ch * 4) * 4,
             A + (size_t)(bm + row) * U_DIM + ch * 4);
    }
    #pragma unroll
    for (int i = 0; i < 4; ++i) {                 // B: 1024 x 16B chunks
        int id = tid + i * 256;
        int kr = id >> 5, rem = id & 31;
        int gate = rem >> 3, ch = rem & 7;
        cp16(sB + (kr * SB + gate * 32 + ch * 4) * 4,
             w + (size_t)(k0 + kr) * N_DIM + gate * U_DIM + bu + ch * 4);
    }
}

// ---------------------------------------------------------------------------
// Fused kernel: tf32 mma.sync GEMM (per-CTA 128m x {i,f,g,o}x32u) + LSTM gating
// ---------------------------------------------------------------------------
__global__ __launch_bounds__(256, 2)
void lstm_fused(const float* __restrict__ x, const float* __restrict__ h,
                const float* __restrict__ c, const float* __restrict__ w,
                float* __restrict__ out) {
    extern __shared__ float smem[];
    const int tid = threadIdx.x;
    const int wid = tid >> 5, lane = tid & 31;
    const int g = lane >> 2, t = lane & 3;
    const int wm = wid >> 2, wn = wid & 3;        // 2 x 4 warp grid
    const int bm = blockIdx.x * BM;
    const int bu = blockIdx.y * BUT;

    float acc[4][4][4];
    #pragma unroll
    for (int mi = 0; mi < 4; ++mi)
        #pragma unroll
        for (int ni = 0; ni < 4; ++ni)
            #pragma unroll
            for (int q = 0; q < 4; ++q) acc[mi][ni][q] = 0.0f;

    // prologue: fill 2 of 3 stages
    load_stage(smem, 0, 0, bm, bu, x, h, w, tid);
    CP_COMMIT();
    load_stage(smem, 1, 1, bm, bu, x, h, w, tid);
    CP_COMMIT();

    int s_cur = 0, s_pre = 2;                     // slot to compute / to prefetch
    for (int kt = 0; kt < NKT; ++kt) {
        CP_WAIT1();                               // stage kt resident
        __syncthreads();                          // everyone done reading slot s_pre
        if (kt + 2 < NKT)
            load_stage(smem, s_pre, kt + 2, bm, bu, x, h, w, tid);
        CP_COMMIT();

        // hoisted per-warp bases
        const float* sa = smem + s_cur * STG_WORDS + (wm * 64 + g) * SA;
        const float* sb = smem + s_cur * STG_WORDS + A_WORDS + t * SB + wn * 32 + g;

        #pragma unroll
        for (int k8 = 0; k8 < 4; ++k8) {
            const int kb = k8 * 8;
            uint32_t af[4][4];
            #pragma unroll
            for (int mi = 0; mi < 4; ++mi) {
                const float* ra = sa + mi * 16 * SA;
                af[mi][0] = f2tf(ra[kb + t]);
                af[mi][1] = f2tf(ra[8 * SA + kb + t]);
                af[mi][2] = f2tf(ra[kb + t + 4]);
                af[mi][3] = f2tf(ra[8 * SA + kb + t + 4]);
            }
            uint32_t bf[4][2];
            #pragma unroll
            for (int ni = 0; ni < 4; ++ni) {
                bf[ni][0] = f2tf(sb[kb * SB + ni * 8]);
                bf[ni][1] = f2tf(sb[(kb + 4) * SB + ni * 8]);
            }
            #pragma unroll
            for (int mi = 0; mi < 4; ++mi)
                #pragma unroll
                for (int ni = 0; ni < 4; ++ni)
                    mma8(acc[mi][ni], af[mi], bf[ni]);
        }

        s_cur = (s_cur + 1 == STAGES) ? 0 : s_cur + 1;
        s_pre = (s_pre + 1 == STAGES) ? 0 : s_pre + 1;
    }

    // ------------- epilogue: gather gates via smem, gate, write out ---------
    __syncthreads();
    float* se = smem;
    #pragma unroll
    for (int mi = 0; mi < 4; ++mi) {
        const int r0 = wm * 64 + mi * 16 + g;
        #pragma unroll
        for (int ni = 0; ni < 4; ++ni) {
            const int cb = wn * 32 + ni * 8 + 2 * t;
            *reinterpret_cast<float2*>(&se[r0 * EP_STRIDE + cb]) =
                make_float2(acc[mi][ni][0], acc[mi][ni][1]);
            *reinterpret_cast<float2*>(&se[(r0 + 8) * EP_STRIDE + cb]) =
                make_float2(acc[mi][ni][2], acc[mi][ni][3]);
        }
    }
    __syncthreads();

    const int BUsz = M_DIM * U_DIM;
    const int c4 = tid & 7;
    #pragma unroll
    for (int rep = 0; rep < 4; ++rep) {
        const int r = (tid >> 3) + rep * 32;
        const float* row = &se[r * EP_STRIDE];
        float4 iv = *reinterpret_cast<const float4*>(row + 0 * 32 + c4 * 4);
        float4 fv = *reinterpret_cast<const float4*>(row + 1 * 32 + c4 * 4);
        float4 gv = *reinterpret_cast<const float4*>(row + 2 * 32 + c4 * 4);
        float4 ov = *reinterpret_cast<const float4*>(row + 3 * 32 + c4 * 4);
        const size_t gidx = (size_t)(bm + r) * U_DIM + bu + c4 * 4;
        float4 cv = *reinterpret_cast<const float4*>(c + gidx);

        float ia[4] = {iv.x, iv.y, iv.z, iv.w};
        float fa[4] = {fv.x, fv.y, fv.z, fv.w};
        float ga[4] = {gv.x, gv.y, gv.z, gv.w};
        float oa[4] = {ov.x, ov.y, ov.z, ov.w};
        float ca[4] = {cv.x, cv.y, cv.z, cv.w};
        float hn[4], cn[4];
        #pragma unroll
        for (int q = 0; q < 4; ++q) {
            float ig = sigmoidf_(ia[q]);
            float fg = sigmoidf_(fa[q]);
            float og = sigmoidf_(oa[q]);
            float gg = tanhf(ga[q]);
            cn[q] = fg * ca[q] + ig * gg;
            hn[q] = og * tanhf(cn[q]);
        }
        float4 h4 = make_float4(hn[0], hn[1], hn[2], hn[3]);
        float4 cc4 = make_float4(cn[0], cn[1], cn[2], cn[3]);
        *reinterpret_cast<float4*>(out + gidx)            = h4;
        *reinterpret_cast<float4*>(out + BUsz + gidx)     = h4;
        *reinterpret_cast<float4*>(out + 2 * BUsz + gidx) = cc4;
    }
}

// ---------------------------------------------------------------------------
extern "C" void kernel_launch(void* const* d_in, const int* in_sizes, int n_in,
                              void* d_out, int out_size) {
    const float* x = (const float*)d_in[0];
    const float* h = (const float*)d_in[1];
    const float* c = (const float*)d_in[2];
    const float* w = (const float*)d_in[3];
    float* out = (float*)d_out;

    static int configured = 0;
    if (!configured) {
        cudaFuncSetAttribute(lstm_fused,
                             cudaFuncAttributeMaxDynamicSharedMemorySize,
                             SMEM_BYTES);
        configured = 1;
    }

    dim3 grid(M_DIM / BM, U_DIM / BUT);   // (8, 64); x fastest -> W L2 reuse
    lstm_fused<<<grid, 256, SMEM_BYTES>>>(x, h, c, w, out);
}

// round 6
// speedup vs baseline: 3.4885x; 1.0536x over previous
#include <cuda_runtime.h>
#include <cstdint>
#include <math.h>

#define M_DIM 1024
#define U_DIM 2048
#define N_DIM 8192
#define K_DIM 4096

#define BM 128
#define BUT 32
#define BK 32
#define STAGES 3
#define SA 40                                // A smem row stride (words)
#define SBW 264                              // B smem row stride (words)
#define A_WORDS (BM * SA)                    // 5120
#define B_WORDS (16 * SBW)                   // 4224
#define STG_WORDS (A_WORDS + B_WORDS)        // 9344
#define SMEM_BYTES (STAGES * STG_WORDS * 4)  // 112128 -> 2 CTAs/SM
#define EP_STRIDE 132
#define NKT (K_DIM / BK)                     // 128

// Packed, tf32-rounded operands (written every launch; deterministic)
__device__ __align__(1024) float  g_a2[(size_t)M_DIM * K_DIM];          // 16 MB
__device__ __align__(1024) float2 g_w2[(size_t)(K_DIM / 2) * N_DIM];    // 134 MB

// ---------------------------------------------------------------------------
__device__ __forceinline__ void cp16(uint32_t dst, const void* src) {
    asm volatile("cp.async.cg.shared.global [%0], [%1], 16;" :: "r"(dst), "l"(src));
}
#define CP_COMMIT() asm volatile("cp.async.commit_group;" ::: "memory")
#define CP_WAIT1()  asm volatile("cp.async.wait_group 1;" ::: "memory")

__device__ __forceinline__ float f2tf_f(float v) {
    uint32_t r;
    asm("cvt.rna.tf32.f32 %0, %1;" : "=r"(r) : "f"(v));
    return __uint_as_float(r);
}

__device__ __forceinline__ void mma8(float* d, const uint32_t* a, const uint32_t* b) {
    asm volatile(
        "mma.sync.aligned.m16n8k8.row.col.f32.tf32.tf32.f32 "
        "{%0,%1,%2,%3}, {%4,%5,%6,%7}, {%8,%9}, {%0,%1,%2,%3};"
        : "+f"(d[0]), "+f"(d[1]), "+f"(d[2]), "+f"(d[3])
        : "r"(a[0]), "r"(a[1]), "r"(a[2]), "r"(a[3]), "r"(b[0]), "r"(b[1]));
}

__device__ __forceinline__ float sigmoidf_(float v) { return 1.0f / (1.0f + expf(-v)); }

// ---------------------------------------------------------------------------
// Pre-pass 1: pack+round A = [x|h] into k-paired layout.
// Packed col j within a 32-k window: j = b*8 + t*2 + sel  ->  k_local = b*8 + t + 4*sel
// ---------------------------------------------------------------------------
__global__ __launch_bounds__(256)
void pack_a(const float* __restrict__ x, const float* __restrict__ h) {
    int idx = blockIdx.x * 256 + threadIdx.x;          // one packed element
    int m = idx >> 12;                                  // /4096
    int j = idx & 4095;
    int kt = j >> 5, q = j & 31;
    int b = q >> 3, t = (q & 7) >> 1, sel = q & 1;
    int k = kt * 32 + b * 8 + t + 4 * sel;
    float v = (k < U_DIM) ? x[(size_t)m * U_DIM + k]
                          : h[(size_t)m * U_DIM + (k - U_DIM)];
    g_a2[(size_t)m * K_DIM + j] = f2tf_f(v);
}

// ---------------------------------------------------------------------------
// Pre-pass 2: pack+round W into k-paired float2 rows.
// Row R = kt*16 + b*4 + t holds pairs (w[kt*32+b*8+t][n], w[kt*32+b*8+t+4][n])
// ---------------------------------------------------------------------------
__global__ __launch_bounds__(256)
void pack_b(const float* __restrict__ w) {
    int idx = blockIdx.x * 256 + threadIdx.x;          // (R, n/4)
    int R = idx >> 11;
    int n = (idx & 2047) << 2;
    int kt = R >> 4, b = (R >> 2) & 3, t = R & 3;
    int k = kt * 32 + b * 8 + t;
    float4 lo = *reinterpret_cast<const float4*>(w + (size_t)k * N_DIM + n);
    float4 hi = *reinterpret_cast<const float4*>(w + (size_t)(k + 4) * N_DIM + n);
    float2* dst = &g_w2[(size_t)R * N_DIM + n];
    dst[0] = make_float2(f2tf_f(lo.x), f2tf_f(hi.x));
    dst[1] = make_float2(f2tf_f(lo.y), f2tf_f(hi.y));
    dst[2] = make_float2(f2tf_f(lo.z), f2tf_f(hi.z));
    dst[3] = make_float2(f2tf_f(lo.w), f2tf_f(hi.w));
}

// ---------------------------------------------------------------------------
// Stage load: A [128 rows x 32 packed], B [16 pair-rows x 4 gates x 32 float2]
// ---------------------------------------------------------------------------
__device__ __forceinline__ void load_stage(float* smem, int s, int kt,
                                           int bm, int bu, int tid) {
    uint32_t sA = (uint32_t)__cvta_generic_to_shared(smem + s * STG_WORDS);
    uint32_t sB = sA + A_WORDS * 4;

    #pragma unroll
    for (int i = 0; i < 4; ++i) {                 // A: 1024 x 16B
        int id = tid + i * 256;
        int row = id >> 3, ch = id & 7;
        cp16(sA + (row * SA + ch * 4) * 4,
             g_a2 + (size_t)(bm + row) * K_DIM + kt * 32 + ch * 4);
    }
    #pragma unroll
    for (int i = 0; i < 4; ++i) {                 // B: 1024 x 16B
        int id = tid + i * 256;
        int r = id >> 6, cc = id & 63;            // 64 chunks per pair-row
        int gate = cc >> 4, ch = cc & 15;
        cp16(sB + (r * SBW + gate * 64 + ch * 4) * 4,
             g_w2 + (size_t)(kt * 16 + r) * N_DIM + gate * U_DIM + bu + ch * 2);
    }
}

// ---------------------------------------------------------------------------
// Fused kernel: tf32 mma.sync GEMM + LSTM gating
// ---------------------------------------------------------------------------
__global__ __launch_bounds__(256, 2)
void lstm_fused(const float* __restrict__ c, float* __restrict__ out) {
    extern __shared__ float smem[];
    const int tid = threadIdx.x;
    const int wid = tid >> 5, lane = tid & 31;
    const int g = lane >> 2, t = lane & 3;
    const int wm = wid >> 2, wn = wid & 3;        // 2 x 4 warp grid
    const int bm = blockIdx.x * BM;
    const int bu = blockIdx.y * BUT;

    float acc[4][4][4];
    #pragma unroll
    for (int mi = 0; mi < 4; ++mi)
        #pragma unroll
        for (int ni = 0; ni < 4; ++ni)
            #pragma unroll
            for (int q = 0; q < 4; ++q) acc[mi][ni][q] = 0.0f;

    load_stage(smem, 0, 0, bm, bu, tid);
    CP_COMMIT();
    load_stage(smem, 1, 1, bm, bu, tid);
    CP_COMMIT();

    int s_cur = 0, s_pre = 2;
    for (int kt = 0; kt < NKT; ++kt) {
        CP_WAIT1();
        __syncthreads();
        if (kt + 2 < NKT)
            load_stage(smem, s_pre, kt + 2, bm, bu, tid);
        CP_COMMIT();

        const float* saW = smem + s_cur * STG_WORDS + (wm * 64 + g) * SA + 2 * t;
        const float* sbW = smem + s_cur * STG_WORDS + A_WORDS + t * SBW + wn * 64 + 2 * g;

        #pragma unroll
        for (int b = 0; b < 4; ++b) {
            uint32_t af[4][4];
            #pragma unroll
            for (int mi = 0; mi < 4; ++mi) {
                float2 a_lo = *reinterpret_cast<const float2*>(saW + mi * 640 + b * 8);
                float2 a_hi = *reinterpret_cast<const float2*>(saW + mi * 640 + 320 + b * 8);
                af[mi][0] = __float_as_uint(a_lo.x);   // A[g][k]
                af[mi][1] = __float_as_uint(a_hi.x);   // A[g+8][k]
                af[mi][2] = __float_as_uint(a_lo.y);   // A[g][k+4]
                af[mi][3] = __float_as_uint(a_hi.y);   // A[g+8][k+4]
            }
            uint32_t bf[4][2];
            #pragma unroll
            for (int ni = 0; ni < 4; ++ni) {
                float2 bp = *reinterpret_cast<const float2*>(sbW + b * (4 * SBW) + ni * 16);
                bf[ni][0] = __float_as_uint(bp.x);     // B[k][n]
                bf[ni][1] = __float_as_uint(bp.y);     // B[k+4][n]
            }
            #pragma unroll
            for (int mi = 0; mi < 4; ++mi)
                #pragma unroll
                for (int ni = 0; ni < 4; ++ni)
                    mma8(acc[mi][ni], af[mi], bf[ni]);
        }

        s_cur = (s_cur + 1 == STAGES) ? 0 : s_cur + 1;
        s_pre = (s_pre + 1 == STAGES) ? 0 : s_pre + 1;
    }

    // ------------- epilogue: gather gates via smem, gate, write out ---------
    __syncthreads();
    float* se = smem;
    #pragma unroll
    for (int mi = 0; mi < 4; ++mi) {
        const int r0 = wm * 64 + mi * 16 + g;
        #pragma unroll
        for (int ni = 0; ni < 4; ++ni) {
            const int cb = wn * 32 + ni * 8 + 2 * t;
            *reinterpret_cast<float2*>(&se[r0 * EP_STRIDE + cb]) =
                make_float2(acc[mi][ni][0], acc[mi][ni][1]);
            *reinterpret_cast<float2*>(&se[(r0 + 8) * EP_STRIDE + cb]) =
                make_float2(acc[mi][ni][2], acc[mi][ni][3]);
        }
    }
    __syncthreads();

    const int BUsz = M_DIM * U_DIM;
    const int c4 = tid & 7;
    #pragma unroll
    for (int rep = 0; rep < 4; ++rep) {
        const int r = (tid >> 3) + rep * 32;
        const float* row = &se[r * EP_STRIDE];
        float4 iv = *reinterpret_cast<const float4*>(row + 0 * 32 + c4 * 4);
        float4 fv = *reinterpret_cast<const float4*>(row + 1 * 32 + c4 * 4);
        float4 gv = *reinterpret_cast<const float4*>(row + 2 * 32 + c4 * 4);
        float4 ov = *reinterpret_cast<const float4*>(row + 3 * 32 + c4 * 4);
        const size_t gidx = (size_t)(bm + r) * U_DIM + bu + c4 * 4;
        float4 cv = *reinterpret_cast<const float4*>(c + gidx);

        float ia[4] = {iv.x, iv.y, iv.z, iv.w};
        float fa[4] = {fv.x, fv.y, fv.z, fv.w};
        float ga[4] = {gv.x, gv.y, gv.z, gv.w};
        float oa[4] = {ov.x, ov.y, ov.z, ov.w};
        float ca[4] = {cv.x, cv.y, cv.z, cv.w};
        float hn[4], cn[4];
        #pragma unroll
        for (int q = 0; q < 4; ++q) {
            float ig = sigmoidf_(ia[q]);
            float fg = sigmoidf_(fa[q]);
            float og = sigmoidf_(oa[q]);
            float gg = tanhf(ga[q]);
            cn[q] = fg * ca[q] + ig * gg;
            hn[q] = og * tanhf(cn[q]);
        }
        float4 h4 = make_float4(hn[0], hn[1], hn[2], hn[3]);
        float4 cc4 = make_float4(cn[0], cn[1], cn[2], cn[3]);
        *reinterpret_cast<float4*>(out + gidx)            = h4;
        *reinterpret_cast<float4*>(out + BUsz + gidx)     = h4;
        *reinterpret_cast<float4*>(out + 2 * BUsz + gidx) = cc4;
    }
}

// ---------------------------------------------------------------------------
extern "C" void kernel_launch(void* const* d_in, const int* in_sizes, int n_in,
                              void* d_out, int out_size) {
    const float* x = (const float*)d_in[0];
    const float* h = (const float*)d_in[1];
    const float* c = (const float*)d_in[2];
    const float* w = (const float*)d_in[3];
    float* out = (float*)d_out;

    static int configured = 0;
    if (!configured) {
        cudaFuncSetAttribute(lstm_fused,
                             cudaFuncAttributeMaxDynamicSharedMemorySize,
                             SMEM_BYTES);
        configured = 1;
    }

    pack_a<<<(M_DIM * K_DIM) / 256, 256>>>(x, h);
    pack_b<<<((K_DIM / 2) * (N_DIM / 4)) / 256, 256>>>(w);

    dim3 grid(M_DIM / BM, U_DIM / BUT);   // (8, 64)
    lstm_fused<<<grid, 256, SMEM_BYTES>>>(c, out);
}

// round 8
// speedup vs baseline: 6.2878x; 1.8025x over previous
#include <cuda_runtime.h>
#include <cuda_fp16.h>
#include <cstdint>
#include <math.h>

#define M_DIM 1024
#define U_DIM 2048
#define N_DIM 8192
#define K_DIM 4096

#define BM 128
#define BUT 32
#define BK 64                                 // k per stage (4 x 16 windows)
#define STAGES 3
#define TGW 264                               // t-group stride in words (1056 B)
#define GRP_PER_STAGE 16                      // 4 windows x 4 t
#define A_WORDS (GRP_PER_STAGE * TGW)         // 4224
#define B_WORDS (GRP_PER_STAGE * TGW)         // 4224
#define STG_WORDS (A_WORDS + B_WORDS)         // 8448
#define SMEM_BYTES (STAGES * STG_WORDS * 4)   // 101376 -> 2 CTAs/SM
#define EP_STRIDE 132
#define NKT (K_DIM / BK)                      // 64

// Packed fp16 operands in fragment order (uint2 = half4)
__device__ __align__(1024) uint2 g_ah[(size_t)M_DIM * K_DIM / 4];   // 8 MB
__device__ __align__(1024) uint2 g_wh[(size_t)N_DIM * K_DIM / 4];   // 64 MB

// ---------------------------------------------------------------------------
__device__ __forceinline__ void cp16(uint32_t dst, const void* src) {
    asm volatile("cp.async.cg.shared.global [%0], [%1], 16;" :: "r"(dst), "l"(src));
}
#define CP_COMMIT() asm volatile("cp.async.commit_group;" ::: "memory")
#define CP_WAIT1()  asm volatile("cp.async.wait_group 1;" ::: "memory")

__device__ __forceinline__ void mma16(float* d, uint32_t a0, uint32_t a1,
                                      uint32_t a2, uint32_t a3,
                                      uint32_t b0, uint32_t b1) {
    asm volatile(
        "mma.sync.aligned.m16n8k16.row.col.f32.f16.f16.f32 "
        "{%0,%1,%2,%3}, {%4,%5,%6,%7}, {%8,%9}, {%0,%1,%2,%3};"
        : "+f"(d[0]), "+f"(d[1]), "+f"(d[2]), "+f"(d[3])
        : "r"(a0), "r"(a1), "r"(a2), "r"(a3), "r"(b0), "r"(b1));
}

__device__ __forceinline__ float sigmoidf_(float v) { return 1.0f / (1.0f + expf(-v)); }

__device__ __forceinline__ uint32_t pack2(float lo, float hi) {
    __half2 p = __floats2half2_rn(lo, hi);
    return *reinterpret_cast<uint32_t*>(&p);
}

// ---------------------------------------------------------------------------
// Pack A=[x|h] -> g_ah[G][m] = half4 {A[m][kb+2t], [kb+2t+1], [kb+2t+8], [kb+2t+9]}
// where G = win*4 + t, kb = win*16.
// ---------------------------------------------------------------------------
__global__ __launch_bounds__(256)
void pack_a(const float* __restrict__ x, const float* __restrict__ h) {
    int idx = blockIdx.x * 256 + threadIdx.x;     // over G * M
    int G = idx >> 10, m = idx & 1023;
    int win = G >> 2, t = G & 3;
    int k = win * 16 + 2 * t;
    const float* A = (k < U_DIM) ? (x + (size_t)m * U_DIM + k)
                                 : (h + (size_t)m * U_DIM + (k - U_DIM));
    uint2 v;
    v.x = pack2(A[0], A[1]);
    v.y = pack2(A[8], A[9]);
    g_ah[(size_t)G * M_DIM + m] = v;
}

// ---------------------------------------------------------------------------
// Pack W -> g_wh[G][n] = half4 {w[kb+2t][n], [kb+2t+1][n], [kb+2t+8][n], [kb+2t+9][n]}
// ---------------------------------------------------------------------------
__global__ __launch_bounds__(256)
void pack_b(const float* __restrict__ w) {
    int idx = blockIdx.x * 256 + threadIdx.x;     // over G * (N/4)
    int G = idx >> 11, n = (idx & 2047) << 2;
    int win = G >> 2, t = G & 3;
    int k = win * 16 + 2 * t;
    const float* r0 = w + (size_t)k * N_DIM + n;
    const float* r1 = r0 + N_DIM;
    const float* r8 = r0 + 8 * (size_t)N_DIM;
    const float* r9 = r0 + 9 * (size_t)N_DIM;
    float4 v0 = *reinterpret_cast<const float4*>(r0);
    float4 v1 = *reinterpret_cast<const float4*>(r1);
    float4 v8 = *reinterpret_cast<const float4*>(r8);
    float4 v9 = *reinterpret_cast<const float4*>(r9);
    uint2* dst = &g_wh[(size_t)G * N_DIM + n];
    dst[0] = make_uint2(pack2(v0.x, v1.x), pack2(v8.x, v9.x));
    dst[1] = make_uint2(pack2(v0.y, v1.y), pack2(v8.y, v9.y));
    dst[2] = make_uint2(pack2(v0.z, v1.z), pack2(v8.z, v9.z));
    dst[3] = make_uint2(pack2(v0.w, v1.w), pack2(v8.w, v9.w));
}

// ---------------------------------------------------------------------------
// Stage load: 16 A groups (128 m x 8B) + 16 B groups (128 n x 8B), 2048 cp16.
// ---------------------------------------------------------------------------
__device__ __forceinline__ void load_stage(float* smem, int s, int kt,
                                           int bm, int bu, int tid) {
    uint32_t sA = (uint32_t)__cvta_generic_to_shared(smem + s * STG_WORDS);
    uint32_t sB = sA + A_WORDS * 4;
    const int g0 = kt * 16;                       // global group base

    #pragma unroll
    for (int i = 0; i < 4; ++i) {                 // A: 1024 chunks
        int id = tid + i * 256;
        int gl = id >> 6, c = id & 63;            // chunk = 2 m rows
        cp16(sA + (gl * TGW + c * 4) * 4,
             &g_ah[(size_t)(g0 + gl) * M_DIM + bm + c * 2]);
    }
    #pragma unroll
    for (int i = 0; i < 4; ++i) {                 // B: 1024 chunks
        int id = tid + i * 256;
        int gl = id >> 6, c = id & 63;            // chunk = 2 n cols
        int nl = c * 2;
        int gate = nl >> 5, u = nl & 31;
        cp16(sB + (gl * TGW + c * 4) * 4,
             &g_wh[(size_t)(g0 + gl) * N_DIM + gate * U_DIM + bu + u]);
    }
}

// ---------------------------------------------------------------------------
// Fused kernel: fp16 mma.sync GEMM (128m x {i,f,g,o}x32u per CTA) + gating
// ---------------------------------------------------------------------------
__global__ __launch_bounds__(256, 2)
void lstm_fused(const float* __restrict__ c, float* __restrict__ out) {
    extern __shared__ float smem[];
    const int tid = threadIdx.x;
    const int wid = tid >> 5, lane = tid & 31;
    const int g = lane >> 2, t = lane & 3;
    const int wm = wid >> 2, wn = wid & 3;        // 2 x 4 warp grid
    const int bm = blockIdx.x * BM;
    const int bu = blockIdx.y * BUT;

    float acc[4][4][4];
    #pragma unroll
    for (int mi = 0; mi < 4; ++mi)
        #pragma unroll
        for (int ni = 0; ni < 4; ++ni)
            #pragma unroll
            for (int q = 0; q < 4; ++q) acc[mi][ni][q] = 0.0f;

    load_stage(smem, 0, 0, bm, bu, tid);
    CP_COMMIT();
    load_stage(smem, 1, 1, bm, bu, tid);
    CP_COMMIT();

    int s_cur = 0, s_pre = 2;
    for (int kt = 0; kt < NKT; ++kt) {
        CP_WAIT1();
        __syncthreads();
        if (kt + 2 < NKT)
            load_stage(smem, s_pre, kt + 2, bm, bu, tid);
        CP_COMMIT();

        const float* stg = smem + s_cur * STG_WORDS;
        #pragma unroll
        for (int w = 0; w < 4; ++w) {             // 4 k-windows of 16
            const float2* pa = reinterpret_cast<const float2*>(
                stg + (w * 4 + t) * TGW) + (wm * 64 + g);
            const float2* pb = reinterpret_cast<const float2*>(
                stg + A_WORDS + (w * 4 + t) * TGW) + (wn * 32 + g);

            uint32_t af[4][4];
            #pragma unroll
            for (int mi = 0; mi < 4; ++mi) {
                float2 lo = pa[mi * 16];          // row g     : {a0, a2}
                float2 hi = pa[mi * 16 + 8];      // row g + 8 : {a1, a3}
                af[mi][0] = __float_as_uint(lo.x);
                af[mi][1] = __float_as_uint(hi.x);
                af[mi][2] = __float_as_uint(lo.y);
                af[mi][3] = __float_as_uint(hi.y);
            }
            uint32_t bf[4][2];
            #pragma unroll
            for (int ni = 0; ni < 4; ++ni) {
                float2 bp = pb[ni * 8];
                bf[ni][0] = __float_as_uint(bp.x);
                bf[ni][1] = __float_as_uint(bp.y);
            }
            #pragma unroll
            for (int mi = 0; mi < 4; ++mi)
                #pragma unroll
                for (int ni = 0; ni < 4; ++ni)
                    mma16(acc[mi][ni], af[mi][0], af[mi][1], af[mi][2], af[mi][3],
                          bf[ni][0], bf[ni][1]);
        }

        s_cur = (s_cur + 1 == STAGES) ? 0 : s_cur + 1;
        s_pre = (s_pre + 1 == STAGES) ? 0 : s_pre + 1;
    }

    // ------------- epilogue: gather gates via smem, gate, write out ---------
    __syncthreads();
    float* se = smem;
    #pragma unroll
    for (int mi = 0; mi < 4; ++mi) {
        const int r0 = wm * 64 + mi * 16 + g;
        #pragma unroll
        for (int ni = 0; ni < 4; ++ni) {
            const int cb = wn * 32 + ni * 8 + 2 * t;
            *reinterpret_cast<float2*>(&se[r0 * EP_STRIDE + cb]) =
                make_float2(acc[mi][ni][0], acc[mi][ni][1]);
            *reinterpret_cast<float2*>(&se[(r0 + 8) * EP_STRIDE + cb]) =
                make_float2(acc[mi][ni][2], acc[mi][ni][3]);
        }
    }
    __syncthreads();

    const int BUsz = M_DIM * U_DIM;
    const int c4 = tid & 7;
    #pragma unroll
    for (int rep = 0; rep < 4; ++rep) {
        const int r = (tid >> 3) + rep * 32;
        const float* row = &se[r * EP_STRIDE];
        float4 iv = *reinterpret_cast<const float4*>(row + 0 * 32 + c4 * 4);
        float4 fv = *reinterpret_cast<const float4*>(row + 1 * 32 + c4 * 4);
        float4 gv = *reinterpret_cast<const float4*>(row + 2 * 32 + c4 * 4);
        float4 ov = *reinterpret_cast<const float4*>(row + 3 * 32 + c4 * 4);
        const size_t gidx = (size_t)(bm + r) * U_DIM + bu + c4 * 4;
        float4 cv = *reinterpret_cast<const float4*>(c + gidx);

        float ia[4] = {iv.x, iv.y, iv.z, iv.w};
        float fa[4] = {fv.x, fv.y, fv.z, fv.w};
        float ga[4] = {gv.x, gv.y, gv.z, gv.w};
        float oa[4] = {ov.x, ov.y, ov.z, ov.w};
        float ca[4] = {cv.x, cv.y, cv.z, cv.w};
        float hn[4], cn[4];
        #pragma unroll
        for (int q = 0; q < 4; ++q) {
            float ig = sigmoidf_(ia[q]);
            float fg = sigmoidf_(fa[q]);
            float og = sigmoidf_(oa[q]);
            float gg = tanhf(ga[q]);
            cn[q] = fg * ca[q] + ig * gg;
            hn[q] = og * tanhf(cn[q]);
        }
        float4 h4 = make_float4(hn[0], hn[1], hn[2], hn[3]);
        float4 cc4 = make_float4(cn[0], cn[1], cn[2], cn[3]);
        *reinterpret_cast<float4*>(out + gidx)            = h4;
        *reinterpret_cast<float4*>(out + BUsz + gidx)     = h4;
        *reinterpret_cast<float4*>(out + 2 * BUsz + gidx) = cc4;
    }
}

// ---------------------------------------------------------------------------
extern "C" void kernel_launch(void* const* d_in, const int* in_sizes, int n_in,
                              void* d_out, int out_size) {
    const float* x = (const float*)d_in[0];
    const float* h = (const float*)d_in[1];
    const float* c = (const float*)d_in[2];
    const float* w = (const float*)d_in[3];
    float* out = (float*)d_out;

    static int configured = 0;
    if (!configured) {
        cudaFuncSetAttribute(lstm_fused,
                             cudaFuncAttributeMaxDynamicSharedMemorySize,
                             SMEM_BYTES);
        configured = 1;
    }

    // pack A: (K/16*4) groups x M elems / 256
    pack_a<<<(K_DIM / 16 * 4 * M_DIM) / 256, 256>>>(x, h);
    // pack W: (K/16*4) groups x N/4 / 256
    pack_b<<<(K_DIM / 16 * 4 * (N_DIM / 4)) / 256, 256>>>(w);

    dim3 grid(M_DIM / BM, U_DIM / BUT);   // (8, 64)
    lstm_fused<<<grid, 256, SMEM_BYTES>>>(c, out);
}

// round 9
// speedup vs baseline: 6.3058x; 1.0029x over previous
#include <cuda_runtime.h>
#include <cuda_fp16.h>
#include <cstdint>
#include <math.h>

#define M_DIM 1024
#define U_DIM 2048
#define N_DIM 8192
#define K_DIM 4096

#define BM 64
#define BUT 32
#define BK 64                                 // k per stage (4 windows of 16)
#define STAGES 3
#define TGA 136                               // A group stride (words)
#define TGB 264                               // B group stride (words)
#define A_WORDS (16 * TGA)                    // 2176
#define B_WORDS (16 * TGB)                    // 4224
#define STG_WORDS (A_WORDS + B_WORDS)         // 6400
#define SMEM_BYTES (STAGES * STG_WORDS * 4)   // 76800 -> 3 CTAs/SM
#define EP_STRIDE 132
#define NKT (K_DIM / BK)                      // 64

// Packed fp16 operands in fragment order (uint2 = half4 {k,k+1,k+8,k+9})
__device__ __align__(1024) uint2 g_ah[(size_t)M_DIM * K_DIM / 4];   // 8 MB
__device__ __align__(1024) uint2 g_wh[(size_t)N_DIM * K_DIM / 4];   // 64 MB

#define PACKA_BLOCKS 4096                     // (M/64) x (K/16)
#define PACKB_BLOCKS 8192

// ---------------------------------------------------------------------------
__device__ __forceinline__ void cp16(uint32_t dst, const void* src) {
    asm volatile("cp.async.cg.shared.global [%0], [%1], 16;" :: "r"(dst), "l"(src));
}
#define CP_COMMIT() asm volatile("cp.async.commit_group;" ::: "memory")
#define CP_WAIT1()  asm volatile("cp.async.wait_group 1;" ::: "memory")

__device__ __forceinline__ void mma16(float* d, uint32_t a0, uint32_t a1,
                                      uint32_t a2, uint32_t a3,
                                      uint32_t b0, uint32_t b1) {
    asm volatile(
        "mma.sync.aligned.m16n8k16.row.col.f32.f16.f16.f32 "
        "{%0,%1,%2,%3}, {%4,%5,%6,%7}, {%8,%9}, {%0,%1,%2,%3};"
        : "+f"(d[0]), "+f"(d[1]), "+f"(d[2]), "+f"(d[3])
        : "r"(a0), "r"(a1), "r"(a2), "r"(a3), "r"(b0), "r"(b1));
}

__device__ __forceinline__ float sigmoidf_(float v) { return 1.0f / (1.0f + expf(-v)); }

__device__ __forceinline__ uint32_t pack2(float lo, float hi) {
    __half2 p = __floats2half2_rn(lo, hi);
    return *reinterpret_cast<uint32_t*>(&p);
}

// ---------------------------------------------------------------------------
// Merged pack kernel.
// Blocks [0, 4096): A pack, coalesced via smem tile transpose.
//   block -> (m0 = (blk&15)*64, win = blk>>4). Tile A[m0..m0+64][win*16..+16).
// Blocks [4096, 12288): W pack (already coalesced).
// ---------------------------------------------------------------------------
__global__ __launch_bounds__(256)
void pack_all(const float* __restrict__ x, const float* __restrict__ h,
              const float* __restrict__ w) {
    if (blockIdx.x < PACKA_BLOCKS) {
        __shared__ float st[64][20];
        int blk = blockIdx.x;
        int m0 = (blk & 15) * 64;
        int win = blk >> 4;
        int k = win * 16;
        const float* A = (k < U_DIM) ? (x + k) : (h + (k - U_DIM));
        int tid = threadIdx.x;
        int row = tid >> 2, q = tid & 3;
        float4 v = *reinterpret_cast<const float4*>(
            A + (size_t)(m0 + row) * U_DIM + q * 4);
        *reinterpret_cast<float4*>(&st[row][q * 4]) = v;
        __syncthreads();
        int t = tid >> 6, ml = tid & 63;
        uint2 o;
        o.x = pack2(st[ml][2 * t], st[ml][2 * t + 1]);
        o.y = pack2(st[ml][2 * t + 8], st[ml][2 * t + 9]);
        g_ah[(size_t)(win * 4 + t) * M_DIM + m0 + ml] = o;
    } else {
        int idx = (blockIdx.x - PACKA_BLOCKS) * 256 + threadIdx.x;
        int G = idx >> 11, n = (idx & 2047) << 2;
        int win = G >> 2, t = G & 3;
        int k = win * 16 + 2 * t;
        const float* r0 = w + (size_t)k * N_DIM + n;
        float4 v0 = *reinterpret_cast<const float4*>(r0);
        float4 v1 = *reinterpret_cast<const float4*>(r0 + N_DIM);
        float4 v8 = *reinterpret_cast<const float4*>(r0 + 8 * (size_t)N_DIM);
        float4 v9 = *reinterpret_cast<const float4*>(r0 + 9 * (size_t)N_DIM);
        uint2* dst = &g_wh[(size_t)G * N_DIM + n];
        dst[0] = make_uint2(pack2(v0.x, v1.x), pack2(v8.x, v9.x));
        dst[1] = make_uint2(pack2(v0.y, v1.y), pack2(v8.y, v9.y));
        dst[2] = make_uint2(pack2(v0.z, v1.z), pack2(v8.z, v9.z));
        dst[3] = make_uint2(pack2(v0.w, v1.w), pack2(v8.w, v9.w));
    }
}

// ---------------------------------------------------------------------------
// Stage load: 16 A groups (64 m x 8B) + 16 B groups (128 n x 8B) = 1536 cp16.
// ---------------------------------------------------------------------------
__device__ __forceinline__ void load_stage(float* smem, int s, int kt,
                                           int bm, int bu, int tid) {
    uint32_t sA = (uint32_t)__cvta_generic_to_shared(smem + s * STG_WORDS);
    uint32_t sB = sA + A_WORDS * 4;
    const int g0 = kt * 16;

    #pragma unroll
    for (int i = 0; i < 2; ++i) {                 // A: 512 chunks
        int id = tid + i * 256;
        int gl = id >> 5, c = id & 31;
        cp16(sA + (gl * TGA + c * 4) * 4,
             &g_ah[(size_t)(g0 + gl) * M_DIM + bm + c * 2]);
    }
    #pragma unroll
    for (int i = 0; i < 4; ++i) {                 // B: 1024 chunks
        int id = tid + i * 256;
        int gl = id >> 6, cB = id & 63;
        int nl = cB * 2;
        int gate = nl >> 5, u = nl & 31;
        cp16(sB + (gl * TGB + cB * 4) * 4,
             &g_wh[(size_t)(g0 + gl) * N_DIM + gate * U_DIM + bu + u]);
    }
}

// ---------------------------------------------------------------------------
// Fused kernel: fp16 mma.sync GEMM (64m x {i,f,g,o}x32u per CTA) + gating
// ---------------------------------------------------------------------------
__global__ __launch_bounds__(256, 3)
void lstm_fused(const float* __restrict__ c, float* __restrict__ out) {
    extern __shared__ float smem[];
    const int tid = threadIdx.x;
    const int wid = tid >> 5, lane = tid & 31;
    const int g = lane >> 2, t = lane & 3;
    const int wm = wid >> 2, wn = wid & 3;        // 2 x 4 warp grid
    const int bm = blockIdx.x * BM;
    const int bu = blockIdx.y * BUT;

    float acc[2][4][4];
    #pragma unroll
    for (int mi = 0; mi < 2; ++mi)
        #pragma unroll
        for (int ni = 0; ni < 4; ++ni)
            #pragma unroll
            for (int q = 0; q < 4; ++q) acc[mi][ni][q] = 0.0f;

    load_stage(smem, 0, 0, bm, bu, tid);
    CP_COMMIT();
    load_stage(smem, 1, 1, bm, bu, tid);
    CP_COMMIT();

    int s_cur = 0, s_pre = 2;
    for (int kt = 0; kt < NKT; ++kt) {
        CP_WAIT1();
        __syncthreads();
        if (kt + 2 < NKT)
            load_stage(smem, s_pre, kt + 2, bm, bu, tid);
        CP_COMMIT();

        const float* stg = smem + s_cur * STG_WORDS;
        #pragma unroll
        for (int w = 0; w < 4; ++w) {
            const float2* pa = reinterpret_cast<const float2*>(
                stg + (w * 4 + t) * TGA) + (wm * 32 + g);
            const float2* pb = reinterpret_cast<const float2*>(
                stg + A_WORDS + (w * 4 + t) * TGB) + (wn * 32 + g);

            uint32_t af[2][4];
            #pragma unroll
            for (int mi = 0; mi < 2; ++mi) {
                float2 lo = pa[mi * 16];
                float2 hi = pa[mi * 16 + 8];
                af[mi][0] = __float_as_uint(lo.x);
                af[mi][1] = __float_as_uint(hi.x);
                af[mi][2] = __float_as_uint(lo.y);
                af[mi][3] = __float_as_uint(hi.y);
            }
            uint32_t bf[4][2];
            #pragma unroll
            for (int ni = 0; ni < 4; ++ni) {
                float2 bp = pb[ni * 8];
                bf[ni][0] = __float_as_uint(bp.x);
                bf[ni][1] = __float_as_uint(bp.y);
            }
            #pragma unroll
            for (int mi = 0; mi < 2; ++mi)
                #pragma unroll
                for (int ni = 0; ni < 4; ++ni)
                    mma16(acc[mi][ni], af[mi][0], af[mi][1], af[mi][2], af[mi][3],
                          bf[ni][0], bf[ni][1]);
        }

        s_cur = (s_cur + 1 == STAGES) ? 0 : s_cur + 1;
        s_pre = (s_pre + 1 == STAGES) ? 0 : s_pre + 1;
    }

    // ------------- epilogue: gather gates via smem, gate, write out ---------
    __syncthreads();
    float* se = smem;
    #pragma unroll
    for (int mi = 0; mi < 2; ++mi) {
        const int r0 = wm * 32 + mi * 16 + g;
        #pragma unroll
        for (int ni = 0; ni < 4; ++ni) {
            const int cb = wn * 32 + ni * 8 + 2 * t;
            *reinterpret_cast<float2*>(&se[r0 * EP_STRIDE + cb]) =
                make_float2(acc[mi][ni][0], acc[mi][ni][1]);
            *reinterpret_cast<float2*>(&se[(r0 + 8) * EP_STRIDE + cb]) =
                make_float2(acc[mi][ni][2], acc[mi][ni][3]);
        }
    }
    __syncthreads();

    const int BUsz = M_DIM * U_DIM;
    const int c4 = tid & 7;
    #pragma unroll
    for (int rep = 0; rep < 2; ++rep) {
        const int r = (tid >> 3) + rep * 32;
        const float* row = &se[r * EP_STRIDE];
        float4 iv = *reinterpret_cast<const float4*>(row + 0 * 32 + c4 * 4);
        float4 fv = *reinterpret_cast<const float4*>(row + 1 * 32 + c4 * 4);
        float4 gv = *reinterpret_cast<const float4*>(row + 2 * 32 + c4 * 4);
        float4 ov = *reinterpret_cast<const float4*>(row + 3 * 32 + c4 * 4);
        const size_t gidx = (size_t)(bm + r) * U_DIM + bu + c4 * 4;
        float4 cv = *reinterpret_cast<const float4*>(c + gidx);

        float ia[4] = {iv.x, iv.y, iv.z, iv.w};
        float fa[4] = {fv.x, fv.y, fv.z, fv.w};
        float ga[4] = {gv.x, gv.y, gv.z, gv.w};
        float oa[4] = {ov.x, ov.y, ov.z, ov.w};
        float ca[4] = {cv.x, cv.y, cv.z, cv.w};
        float hn[4], cn[4];
        #pragma unroll
        for (int q = 0; q < 4; ++q) {
            float ig = sigmoidf_(ia[q]);
            float fg = sigmoidf_(fa[q]);
            float og = sigmoidf_(oa[q]);
            float gg = tanhf(ga[q]);
            cn[q] = fg * ca[q] + ig * gg;
            hn[q] = og * tanhf(cn[q]);
        }
        float4 h4 = make_float4(hn[0], hn[1], hn[2], hn[3]);
        float4 cc4 = make_float4(cn[0], cn[1], cn[2], cn[3]);
        *reinterpret_cast<float4*>(out + gidx)            = h4;
        *reinterpret_cast<float4*>(out + BUsz + gidx)     = h4;
        *reinterpret_cast<float4*>(out + 2 * BUsz + gidx) = cc4;
    }
}

// ---------------------------------------------------------------------------
extern "C" void kernel_launch(void* const* d_in, const int* in_sizes, int n_in,
                              void* d_out, int out_size) {
    const float* x = (const float*)d_in[0];
    const float* h = (const float*)d_in[1];
    const float* c = (const float*)d_in[2];
    const float* w = (const float*)d_in[3];
    float* out = (float*)d_out;

    static int configured = 0;
    if (!configured) {
        cudaFuncSetAttribute(lstm_fused,
                             cudaFuncAttributeMaxDynamicSharedMemorySize,
                             SMEM_BYTES);
        configured = 1;
    }

    pack_all<<<PACKA_BLOCKS + PACKB_BLOCKS, 256>>>(x, h, w);

    dim3 grid(M_DIM / BM, U_DIM / BUT);   // (16, 64); x fastest -> W L2 reuse
    lstm_fused<<<grid, 256, SMEM_BYTES>>>(c, out);
}